// round 3
// baseline (speedup 1.0000x reference)
#include <cuda_runtime.h>
#include <cuda_bf16.h>
#include <stdint.h>

// Inputs (metadata order):
//   d_in[0]: inputs_t  int32  [1, 17400]
//   d_in[1]: indices   int32  [N_SYN, 2]  -> (post, pre) per row
//   d_in[2]: weights   float32 [N_SYN]
//   d_in[3]: n_post    (scalar; we use out_size instead)
// Output: float32 [1, n_post]

__global__ void zero_out_kernel(float* __restrict__ out, int n) {
    int i = blockIdx.x * blockDim.x + threadIdx.x;
    if (i < n) out[i] = 0.0f;
}

// 4 synapses per thread: two int4 index loads + one float4 weight load.
// Atomic is predicated on activity (skips ~50% of atomics).
__global__ void __launch_bounds__(256) scatter4_kernel(
    const int*    __restrict__ act,    // inputs_t, 17400 ints (L1-resident)
    const int4*   __restrict__ idx4,   // (post0,pre0,post1,pre1) pairs
    const float4* __restrict__ w4,
    float*        __restrict__ out,
    int n_quads)                        // n_syn / 4
{
    int i = blockIdx.x * blockDim.x + threadIdx.x;
    if (i >= n_quads) return;

    int4   a  = idx4[2 * i];
    int4   b  = idx4[2 * i + 1];
    float4 wv = w4[i];

    if (act[a.y] > 0) atomicAdd(out + a.x, wv.x);
    if (act[a.w] > 0) atomicAdd(out + a.z, wv.y);
    if (act[b.y] > 0) atomicAdd(out + b.x, wv.z);
    if (act[b.w] > 0) atomicAdd(out + b.z, wv.w);
}

// Tail for n_syn not divisible by 4 (not hit for N_SYN=30M, kept for safety).
__global__ void scatter_tail_kernel(
    const int*  __restrict__ act,
    const int2* __restrict__ idx2,
    const float* __restrict__ w,
    float*       __restrict__ out,
    int start, int n_syn)
{
    int i = start + blockIdx.x * blockDim.x + threadIdx.x;
    if (i >= n_syn) return;
    int2 p = idx2[i];
    if (act[p.y] > 0) atomicAdd(out + p.x, w[i]);
}

extern "C" void kernel_launch(void* const* d_in, const int* in_sizes, int n_in,
                              void* d_out, int out_size) {
    const int*   act     = (const int*)d_in[0];
    const int*   indices = (const int*)d_in[1];
    const float* weights = (const float*)d_in[2];
    float*       out     = (float*)d_out;

    const int n_syn = in_sizes[2];   // weights element count

    // Zero the output (poisoned to 0xAA by harness).
    {
        int threads = 256;
        int blocks  = (out_size + threads - 1) / threads;
        zero_out_kernel<<<blocks, threads>>>(out, out_size);
    }

    const int n_quads = n_syn / 4;
    if (n_quads > 0) {
        int threads = 256;
        int blocks  = (n_quads + threads - 1) / threads;
        scatter4_kernel<<<blocks, threads>>>(
            act, (const int4*)indices, (const float4*)weights, out, n_quads);
    }

    const int done = n_quads * 4;
    if (done < n_syn) {
        int rem = n_syn - done;
        int threads = 256;
        int blocks  = (rem + threads - 1) / threads;
        scatter_tail_kernel<<<blocks, threads>>>(
            act, (const int2*)indices, weights, out, done, n_syn);
    }
}